// round 8
// baseline (speedup 1.0000x reference)
#include <cuda_runtime.h>

#define NN 100000
#define EE 500000
#define DD 128
#define RR 10
#define EPS 1e-5f

// ---------------- scratch (device globals; no allocation allowed) ----------
__device__ float g_agg_in [NN * DD];
__device__ float g_agg_out[NN * DD];
__device__ float g_out    [NN * DD];
__device__ float g_x      [NN * DD];
__device__ int   g_deg_s  [NN];
__device__ int   g_deg_d  [NN];
__device__ float g_dinv_s [NN];
__device__ float g_dinv_d [NN];
__device__ int   g_off_s  [NN + 1];
__device__ int   g_off_d  [NN + 1];
__device__ int   g_cur_s  [NN];
__device__ int   g_cur_d  [NN];
__device__ int   g_nbr_in [EE];   // packed (type<<20)|dst, grouped by src
__device__ int   g_nbr_out[EE];   // packed (type<<20)|src, grouped by dst
__device__ float g_stats  [3][2 * DD];   // [2] = probe dummy slot
__device__ float g_r1     [RR * DD];
__device__ int   g_part   [2][256];
__device__ int   g_partpre[2][256];

#define SCAN_B   512
#define SCAN_NB  ((NN + SCAN_B - 1) / SCAN_B)   // 196

// ---------------- small helpers -------------------------------------------
__device__ __forceinline__ unsigned long long pk2(float lo, float hi) {
    unsigned long long r;
    asm("mov.b64 %0, {%1, %2};" : "=l"(r) : "f"(lo), "f"(hi));
    return r;
}
__device__ __forceinline__ void upk2(unsigned long long v, float& lo, float& hi) {
    asm("mov.b64 {%0, %1}, %2;" : "=f"(lo), "=f"(hi) : "l"(v));
}
__device__ __forceinline__ void fma2(unsigned long long& d,
                                     unsigned long long a, unsigned long long b) {
    asm("fma.rn.f32x2 %0, %1, %2, %0;" : "+l"(d) : "l"(a), "l"(b));
}
__device__ __forceinline__ float fast_tanh(float x) {
    float e = __expf(2.0f * x);
    return __fdividef(e - 1.0f, e + 1.0f);
}

// ---------------- degree precompute ----------------------------------------
__global__ void k_zero_deg() {
    int i = blockIdx.x * blockDim.x + threadIdx.x;
    int stride = gridDim.x * blockDim.x;
    for (int n = i; n < NN; n += stride) { g_deg_s[n] = 0; g_deg_d[n] = 0; }
    if (i < 6 * DD) ((float*)g_stats)[i] = 0.f;
}

__global__ void k_degree(const int* __restrict__ src, const int* __restrict__ dst) {
    int e = blockIdx.x * blockDim.x + threadIdx.x;
    if (e < EE) {
        atomicAdd(&g_deg_s[src[e]], 1);
        atomicAdd(&g_deg_d[dst[e]], 1);
    }
}

__global__ void k_dinv() {
    int n = blockIdx.x * blockDim.x + threadIdx.x;
    if (n < NN) {
        int ds = g_deg_s[n], dd = g_deg_d[n];
        g_dinv_s[n] = (ds > 0) ? rsqrtf((float)ds) : 0.0f;
        g_dinv_d[n] = (dd > 0) ? rsqrtf((float)dd) : 0.0f;
    }
}

// ---------------- 3-phase CSR scan -----------------------------------------
__global__ void k_scan_part() {
    const int which = blockIdx.y;
    const int* __restrict__ deg = which ? g_deg_d : g_deg_s;
    int idx = blockIdx.x * SCAN_B + threadIdx.x;
    int v = (idx < NN) ? deg[idx] : 0;
    __shared__ int sm[SCAN_B];
    sm[threadIdx.x] = v;
    __syncthreads();
    for (int o = SCAN_B / 2; o > 0; o >>= 1) {
        if (threadIdx.x < o) sm[threadIdx.x] += sm[threadIdx.x + o];
        __syncthreads();
    }
    if (threadIdx.x == 0) g_part[which][blockIdx.x] = sm[0];
}

__global__ void k_scan_top() {
    int which = threadIdx.x >> 8;
    int t = threadIdx.x & 255;
    __shared__ int sm[2][256];
    sm[which][t] = (t < SCAN_NB) ? g_part[which][t] : 0;
    __syncthreads();
    for (int o = 1; o < 256; o <<= 1) {
        int v = (t >= o) ? sm[which][t - o] : 0;
        __syncthreads();
        sm[which][t] += v;
        __syncthreads();
    }
    int self = (t < SCAN_NB) ? g_part[which][t] : 0;
    g_partpre[which][t] = sm[which][t] - self;
    if (threadIdx.x == 0) { g_off_s[NN] = EE; g_off_d[NN] = EE; }
}

__global__ void k_scan_fix() {
    const int which = blockIdx.y;
    const int* __restrict__ deg = which ? g_deg_d : g_deg_s;
    int* __restrict__ off = which ? g_off_d : g_off_s;
    int* __restrict__ cur = which ? g_cur_d : g_cur_s;
    int t = threadIdx.x;
    int idx = blockIdx.x * SCAN_B + t;
    int v = (idx < NN) ? deg[idx] : 0;
    __shared__ int sm[SCAN_B];
    sm[t] = v;
    __syncthreads();
    for (int o = 1; o < SCAN_B; o <<= 1) {
        int u = (t >= o) ? sm[t - o] : 0;
        __syncthreads();
        sm[t] += u;
        __syncthreads();
    }
    if (idx < NN) {
        int base = g_partpre[which][blockIdx.x];
        int e = base + sm[t] - v;
        off[idx] = e;
        cur[idx] = e;
    }
}

__global__ void k_scatter(const int* __restrict__ src, const int* __restrict__ dst,
                          const int* __restrict__ typ) {
    int e = blockIdx.x * blockDim.x + threadIdx.x;
    if (e < EE) {
        int s = src[e], d = dst[e], t = typ[e];
        int p0 = atomicAdd(&g_cur_s[s], 1);
        g_nbr_in[p0] = (t << 20) | d;
        int p1 = atomicAdd(&g_cur_d[d], 1);
        g_nbr_out[p1] = (t << 20) | s;
    }
}

// ---------------- gather aggregation: warp per (node, direction) ------------
__global__ __launch_bounds__(256)
void k_agg(const float* __restrict__ x, const float* __restrict__ r) {
    __shared__ float rs[RR * DD];
    for (int i = threadIdx.x; i < RR * DD; i += blockDim.x) rs[i] = r[i];
    __syncthreads();

    int gwarp = (blockIdx.x * blockDim.x + threadIdx.x) >> 5;
    int lane  = threadIdx.x & 31;
    if (gwarp >= 2 * NN) return;
    int dir = gwarp >= NN;
    int n   = gwarp - (dir ? NN : 0);

    const int*   __restrict__ off  = dir ? g_off_d  : g_off_s;
    const int*   __restrict__ nbr  = dir ? g_nbr_out : g_nbr_in;
    const float* __restrict__ dinv = dir ? g_dinv_d : g_dinv_s;
    float*       __restrict__ agg  = dir ? g_agg_out : g_agg_in;

    const float4* x4 = (const float4*)x;
    int beg = off[n], end = off[n + 1];

    float4 acc = make_float4(0.f, 0.f, 0.f, 0.f);
    for (int p = beg; p < end; p++) {
        int pk = nbr[p];
        int m = pk & 0xFFFFF;
        int t = pk >> 20;
        float dv = dinv[m];
        float4 xv = x4[m * 32 + lane];
        float4 rv = *(const float4*)&rs[t * DD + lane * 4];
        acc.x += dv * xv.x * rv.x;
        acc.y += dv * xv.y * rv.y;
        acc.z += dv * xv.z * rv.z;
        acc.w += dv * xv.w * rv.w;
    }
    float own = dinv[n];
    acc.x *= own; acc.y *= own; acc.z *= own; acc.w *= own;
    *(float4*)&agg[(size_t)n * DD + lane * 4] = acc;
}

// ---------------- fused 3-chunk GEMM + bias + BN partial stats --------------
__global__ __launch_bounds__(256)
void k_gemm(const float* __restrict__ x,
            const float* __restrict__ B0, const float* __restrict__ B1,
            const float* __restrict__ B2,
            const float* __restrict__ lr, const float* __restrict__ bias,
            int layer) {
    __shared__ float Ast[32][132];   // [k][row], transposed
    __shared__ float Bs [32][132];   // [k][col]

    const int tid = threadIdx.x;
    const int tx = tid & 15;
    const int ty = tid >> 4;
    const int rowBase = blockIdx.x * 128;

    unsigned long long acc[8][4];
#pragma unroll
    for (int i = 0; i < 8; i++)
#pragma unroll
        for (int j = 0; j < 4; j++) acc[i][j] = 0ULL;

    for (int c = 0; c < 3; c++) {
        const float* A = (c == 0) ? g_agg_in : (c == 1) ? g_agg_out : x;
        const float* B = (c == 0) ? B0 : (c == 1) ? B1 : B2;
        for (int ks = 0; ks < 4; ks++) {
            __syncthreads();
            {   // A slice: 128 rows x 32 k (transposed store)
                int k4 = tid & 7;
                int r0 = tid >> 3;
#pragma unroll
                for (int rr = 0; rr < 4; rr++) {
                    int row = r0 + rr * 32;
                    int grow = rowBase + row;
                    float4 v = make_float4(0.f, 0.f, 0.f, 0.f);
                    if (grow < NN)
                        v = *(const float4*)&A[(size_t)grow * DD + ks * 32 + k4 * 4];
                    Ast[k4 * 4 + 0][row] = v.x;
                    Ast[k4 * 4 + 1][row] = v.y;
                    Ast[k4 * 4 + 2][row] = v.z;
                    Ast[k4 * 4 + 3][row] = v.w;
                }
            }
            {   // B slice: 32 k x 128 col
                int c4 = tid & 31;
                int k0 = tid >> 5;
#pragma unroll
                for (int p = 0; p < 4; p++) {
                    int kk = k0 + p * 8;
                    int gk = ks * 32 + kk;
                    float4 v = *(const float4*)&B[gk * DD + c4 * 4];
                    if (c == 2) {
                        float sc = lr[gk];
                        v.x *= sc; v.y *= sc; v.z *= sc; v.w *= sc;
                    }
                    *(float4*)&Bs[kk][c4 * 4] = v;
                }
            }
            __syncthreads();
#pragma unroll 4
            for (int k = 0; k < 32; k++) {
                float4 a0 = *(const float4*)&Ast[k][ty * 8];
                float4 a1 = *(const float4*)&Ast[k][ty * 8 + 4];
                float4 b0 = *(const float4*)&Bs[k][tx * 8];
                float4 b1 = *(const float4*)&Bs[k][tx * 8 + 4];
                unsigned long long bp[4];
                bp[0] = pk2(b0.x, b0.y); bp[1] = pk2(b0.z, b0.w);
                bp[2] = pk2(b1.x, b1.y); bp[3] = pk2(b1.z, b1.w);
                float av[8] = {a0.x, a0.y, a0.z, a0.w, a1.x, a1.y, a1.z, a1.w};
#pragma unroll
                for (int i = 0; i < 8; i++) {
                    unsigned long long ap = pk2(av[i], av[i]);
#pragma unroll
                    for (int j = 0; j < 4; j++) fma2(acc[i][j], ap, bp[j]);
                }
            }
        }
    }

    // epilogue: scale + bias + store + BN partial stats
    const float third = 1.0f / 3.0f;
    float scol[8], qcol[8];
#pragma unroll
    for (int jj = 0; jj < 8; jj++) { scol[jj] = 0.f; qcol[jj] = 0.f; }
#pragma unroll
    for (int i = 0; i < 8; i++) {
        int grow = rowBase + ty * 8 + i;
        if (grow < NN) {
#pragma unroll
            for (int j = 0; j < 4; j++) {
                float lo, hi;
                upk2(acc[i][j], lo, hi);
                int col = tx * 8 + j * 2;
                lo = lo * third + bias[col];
                hi = hi * third + bias[col + 1];
                g_out[(size_t)grow * DD + col]     = lo;
                g_out[(size_t)grow * DD + col + 1] = hi;
                scol[j * 2]     += lo;  qcol[j * 2]     += lo * lo;
                scol[j * 2 + 1] += hi;  qcol[j * 2 + 1] += hi * hi;
            }
        }
    }

    __syncthreads();
    float* ssum = &Ast[0][0];
    float* ssq  = &Ast[0][0] + DD;
    if (tid < DD) { ssum[tid] = 0.f; ssq[tid] = 0.f; }
    __syncthreads();
#pragma unroll
    for (int jj = 0; jj < 8; jj++) {
        int col = tx * 8 + jj;
        atomicAdd(&ssum[col], scol[jj]);
        atomicAdd(&ssq[col], qcol[jj]);
    }
    __syncthreads();
    if (tid < DD) {
        atomicAdd(&g_stats[layer][tid], ssum[tid]);
        atomicAdd(&g_stats[layer][DD + tid], ssq[tid]);
    }
}

// ---------------- batchnorm normalize + fast tanh (float4) ------------------
__global__ __launch_bounds__(256)
void k_bn_tanh(float* __restrict__ xo, int layer) {
    int cg = threadIdx.x & 31;          // float4 column group
    int rr = threadIdx.x >> 5;          // 0..7
    int c0 = cg * 4;
    float m0 = g_stats[layer][c0],     m1 = g_stats[layer][c0 + 1];
    float m2 = g_stats[layer][c0 + 2], m3 = g_stats[layer][c0 + 3];
    float q0 = g_stats[layer][DD + c0],     q1 = g_stats[layer][DD + c0 + 1];
    float q2 = g_stats[layer][DD + c0 + 2], q3 = g_stats[layer][DD + c0 + 3];
    const float invN = 1.0f / NN;
    m0 *= invN; m1 *= invN; m2 *= invN; m3 *= invN;
    float i0 = rsqrtf(q0 * invN - m0 * m0 + EPS);
    float i1 = rsqrtf(q1 * invN - m1 * m1 + EPS);
    float i2 = rsqrtf(q2 * invN - m2 * m2 + EPS);
    float i3 = rsqrtf(q3 * invN - m3 * m3 + EPS);
    for (int n = blockIdx.x * 8 + rr; n < NN; n += gridDim.x * 8) {
        float4 v = *(const float4*)&g_out[(size_t)n * DD + c0];
        v.x = fast_tanh((v.x - m0) * i0);
        v.y = fast_tanh((v.y - m1) * i1);
        v.z = fast_tanh((v.z - m2) * i2);
        v.w = fast_tanh((v.w - m3) * i3);
        *(float4*)&xo[(size_t)n * DD + c0] = v;
    }
}

// ---------------- relation transform r' = r @ W -----------------------------
__global__ void k_relmm(const float* __restrict__ r, const float* __restrict__ w,
                        float* __restrict__ ro) {
    int idx = blockIdx.x * blockDim.x + threadIdx.x;
    if (idx < RR * DD) {
        int i = idx / DD, j = idx % DD;
        float s = 0.f;
        for (int k = 0; k < DD; k++) s += r[i * DD + k] * w[k * DD + j];
        ro[idx] = s;
    }
}

// ---------------- launch ----------------------------------------------------
extern "C" void kernel_launch(void* const* d_in, const int* in_sizes, int n_in,
                              void* d_out, int out_size) {
    const float* x0       = (const float*)d_in[0];
    const float* r0       = (const float*)d_in[1];
    const float* w_in     = (const float*)d_in[2];
    const float* w_out    = (const float*)d_in[3];
    const float* w_loop   = (const float*)d_in[4];
    const float* w_rel    = (const float*)d_in[5];
    const float* loop_rel = (const float*)d_in[6];
    const float* bias     = (const float*)d_in[7];
    const int*   esrc     = (const int*)d_in[8];
    const int*   edst     = (const int*)d_in[9];
    const int*   etyp     = (const int*)d_in[10];

    float* out      = (float*)d_out;
    float* x_final  = out;
    float* r_final  = out + (size_t)NN * DD;

    const int GEMM_BLOCKS = (NN + 127) / 128;          // 782
    const int AGG_BLOCKS  = (2 * NN + 7) / 8;

    // launch idx 0..2: precompute
    k_zero_deg<<<256, 256>>>();
    k_degree<<<(EE + 255) / 256, 256>>>(esrc, edst);
    k_dinv<<<(NN + 255) / 256, 256>>>();

    // launch idx 3: *** ncu PROBE *** — full-size GEMM on scratch buffers.
    // Writes g_out (fully overwritten by the real layer-0 GEMM below) and
    // dummy stats slot [2]. Output-correctness unaffected.
    k_gemm<<<GEMM_BLOCKS, 256>>>(x0, w_in, w_out, w_loop, loop_rel, bias, 2);

    {
        dim3 g(SCAN_NB, 2);
        k_scan_part<<<g, SCAN_B>>>();
        k_scan_top<<<1, 512>>>();
        k_scan_fix<<<g, SCAN_B>>>();
    }
    k_scatter<<<(EE + 255) / 256, 256>>>(esrc, edst, etyp);

    // ---- layer 0 ----
    k_agg<<<AGG_BLOCKS, 256>>>(x0, r0);
    k_gemm<<<GEMM_BLOCKS, 256>>>(x0, w_in, w_out, w_loop, loop_rel, bias, 0);
    k_bn_tanh<<<512, 256>>>(g_x, 0);
    k_relmm<<<(RR * DD + 255) / 256, 256>>>(r0, w_rel, g_r1);

    // ---- layer 1 ----
    k_agg<<<AGG_BLOCKS, 256>>>(g_x, g_r1);
    k_gemm<<<GEMM_BLOCKS, 256>>>(g_x, w_in + DD * DD, w_out + DD * DD,
                                 w_loop + DD * DD, loop_rel + DD, bias + DD, 1);
    k_bn_tanh<<<512, 256>>>(x_final, 1);
    k_relmm<<<(RR * DD + 255) / 256, 256>>>(g_r1, w_rel + DD * DD, r_final);
}

// round 9
// speedup vs baseline: 1.1086x; 1.1086x over previous
#include <cuda_runtime.h>

#define NN 100000
#define EE 500000
#define DD 128
#define RR 10
#define EPS 1e-5f

// ---------------- scratch (device globals; no allocation allowed) ----------
__device__ float g_agg_in [NN * DD];
__device__ float g_agg_out[NN * DD];
__device__ float g_out    [NN * DD];
__device__ float g_x      [NN * DD];
__device__ int   g_deg_s  [NN];
__device__ int   g_deg_d  [NN];
__device__ float g_dinv_s [NN];
__device__ float g_dinv_d [NN];
__device__ int   g_off_s  [NN + 1];
__device__ int   g_off_d  [NN + 1];
__device__ int   g_cur_s  [NN];
__device__ int   g_cur_d  [NN];
__device__ int   g_nbr_in [EE];   // packed (type<<20)|dst, grouped by src
__device__ int   g_nbr_out[EE];   // packed (type<<20)|src, grouped by dst
__device__ float g_stats  [3][2 * DD];
__device__ float g_r1     [RR * DD];
__device__ int   g_part   [2][256];
__device__ int   g_partpre[2][256];

#define SCAN_B   512
#define SCAN_NB  ((NN + SCAN_B - 1) / SCAN_B)   // 196

// ---------------- small helpers -------------------------------------------
__device__ __forceinline__ unsigned long long pk2(float lo, float hi) {
    unsigned long long r;
    asm("mov.b64 %0, {%1, %2};" : "=l"(r) : "f"(lo), "f"(hi));
    return r;
}
__device__ __forceinline__ void upk2(unsigned long long v, float& lo, float& hi) {
    asm("mov.b64 {%0, %1}, %2;" : "=f"(lo), "=f"(hi) : "l"(v));
}
__device__ __forceinline__ void fma2(unsigned long long& d,
                                     unsigned long long a, unsigned long long b) {
    asm("fma.rn.f32x2 %0, %1, %2, %0;" : "+l"(d) : "l"(a), "l"(b));
}
__device__ __forceinline__ float fast_tanh(float x) {
    float e = __expf(2.0f * x);
    return __fdividef(e - 1.0f, e + 1.0f);
}

// ---------------- degree precompute ----------------------------------------
__global__ void k_zero_deg() {
    int i = blockIdx.x * blockDim.x + threadIdx.x;
    int stride = gridDim.x * blockDim.x;
    for (int n = i; n < NN; n += stride) { g_deg_s[n] = 0; g_deg_d[n] = 0; }
    if (i < 6 * DD) ((float*)g_stats)[i] = 0.f;
}

// ---------------- fake CSR for the ncu probe (uniform degree 5, hashed) -----
__global__ void k_fake_csr(int which) {
    int* __restrict__ off   = which ? g_off_d : g_off_s;
    float* __restrict__ din = which ? g_dinv_d : g_dinv_s;
    int* __restrict__ nbr   = which ? g_nbr_out : g_nbr_in;
    int i = blockIdx.x * blockDim.x + threadIdx.x;
    int stride = gridDim.x * blockDim.x;
    const int DEG = EE / NN;                 // 5
    for (int n = i; n < NN; n += stride) { off[n] = DEG * n; din[n] = 0.4472136f; }
    if (i == 0) off[NN] = EE;
    for (int p = i; p < EE; p += stride) {
        unsigned h = (unsigned)p * 2654435761u;
        nbr[p] = (int)(h % NN) | ((p % RR) << 20);
    }
}

__global__ void k_degree(const int* __restrict__ src, const int* __restrict__ dst) {
    int e = blockIdx.x * blockDim.x + threadIdx.x;
    if (e < EE) {
        atomicAdd(&g_deg_s[src[e]], 1);
        atomicAdd(&g_deg_d[dst[e]], 1);
    }
}

__global__ void k_dinv() {
    int n = blockIdx.x * blockDim.x + threadIdx.x;
    if (n < NN) {
        int ds = g_deg_s[n], dd = g_deg_d[n];
        g_dinv_s[n] = (ds > 0) ? rsqrtf((float)ds) : 0.0f;
        g_dinv_d[n] = (dd > 0) ? rsqrtf((float)dd) : 0.0f;
    }
}

// ---------------- 3-phase CSR scan -----------------------------------------
__global__ void k_scan_part() {
    const int which = blockIdx.y;
    const int* __restrict__ deg = which ? g_deg_d : g_deg_s;
    int idx = blockIdx.x * SCAN_B + threadIdx.x;
    int v = (idx < NN) ? deg[idx] : 0;
    __shared__ int sm[SCAN_B];
    sm[threadIdx.x] = v;
    __syncthreads();
    for (int o = SCAN_B / 2; o > 0; o >>= 1) {
        if (threadIdx.x < o) sm[threadIdx.x] += sm[threadIdx.x + o];
        __syncthreads();
    }
    if (threadIdx.x == 0) g_part[which][blockIdx.x] = sm[0];
}

__global__ void k_scan_top() {
    int which = threadIdx.x >> 8;
    int t = threadIdx.x & 255;
    __shared__ int sm[2][256];
    sm[which][t] = (t < SCAN_NB) ? g_part[which][t] : 0;
    __syncthreads();
    for (int o = 1; o < 256; o <<= 1) {
        int v = (t >= o) ? sm[which][t - o] : 0;
        __syncthreads();
        sm[which][t] += v;
        __syncthreads();
    }
    int self = (t < SCAN_NB) ? g_part[which][t] : 0;
    g_partpre[which][t] = sm[which][t] - self;
    if (threadIdx.x == 0) { g_off_s[NN] = EE; g_off_d[NN] = EE; }
}

__global__ void k_scan_fix() {
    const int which = blockIdx.y;
    const int* __restrict__ deg = which ? g_deg_d : g_deg_s;
    int* __restrict__ off = which ? g_off_d : g_off_s;
    int* __restrict__ cur = which ? g_cur_d : g_cur_s;
    int t = threadIdx.x;
    int idx = blockIdx.x * SCAN_B + t;
    int v = (idx < NN) ? deg[idx] : 0;
    __shared__ int sm[SCAN_B];
    sm[t] = v;
    __syncthreads();
    for (int o = 1; o < SCAN_B; o <<= 1) {
        int u = (t >= o) ? sm[t - o] : 0;
        __syncthreads();
        sm[t] += u;
        __syncthreads();
    }
    if (idx < NN) {
        int base = g_partpre[which][blockIdx.x];
        int e = base + sm[t] - v;
        off[idx] = e;
        cur[idx] = e;
    }
}

__global__ void k_scatter(const int* __restrict__ src, const int* __restrict__ dst,
                          const int* __restrict__ typ) {
    int e = blockIdx.x * blockDim.x + threadIdx.x;
    if (e < EE) {
        int s = src[e], d = dst[e], t = typ[e];
        int p0 = atomicAdd(&g_cur_s[s], 1);
        g_nbr_in[p0] = (t << 20) | d;
        int p1 = atomicAdd(&g_cur_d[d], 1);
        g_nbr_out[p1] = (t << 20) | s;
    }
}

// ---------------- gather aggregation: warp per (node, direction) ------------
// 4-way software pipeline to raise MLP on the random x-row gathers.
__global__ __launch_bounds__(256)
void k_agg(const float* __restrict__ x, const float* __restrict__ r) {
    __shared__ float rs[RR * DD];
    for (int i = threadIdx.x; i < RR * DD; i += blockDim.x) rs[i] = r[i];
    __syncthreads();

    int gwarp = (blockIdx.x * blockDim.x + threadIdx.x) >> 5;
    int lane  = threadIdx.x & 31;
    if (gwarp >= 2 * NN) return;
    int dir = gwarp >= NN;
    int n   = gwarp - (dir ? NN : 0);

    const int*   __restrict__ off  = dir ? g_off_d  : g_off_s;
    const int*   __restrict__ nbr  = dir ? g_nbr_out : g_nbr_in;
    const float* __restrict__ dinv = dir ? g_dinv_d : g_dinv_s;
    float*       __restrict__ agg  = dir ? g_agg_out : g_agg_in;

    const float4* x4 = (const float4*)x;
    int beg = off[n], end = off[n + 1];

    float4 acc = make_float4(0.f, 0.f, 0.f, 0.f);
    int p = beg;
    for (; p + 4 <= end; p += 4) {
        int pk0 = nbr[p], pk1 = nbr[p + 1], pk2 = nbr[p + 2], pk3 = nbr[p + 3];
        int m0 = pk0 & 0xFFFFF, m1 = pk1 & 0xFFFFF, m2 = pk2 & 0xFFFFF, m3 = pk3 & 0xFFFFF;
        float dv0 = dinv[m0], dv1 = dinv[m1], dv2 = dinv[m2], dv3 = dinv[m3];
        float4 xv0 = x4[m0 * 32 + lane];
        float4 xv1 = x4[m1 * 32 + lane];
        float4 xv2 = x4[m2 * 32 + lane];
        float4 xv3 = x4[m3 * 32 + lane];
        float4 rv0 = *(const float4*)&rs[(pk0 >> 20) * DD + lane * 4];
        float4 rv1 = *(const float4*)&rs[(pk1 >> 20) * DD + lane * 4];
        float4 rv2 = *(const float4*)&rs[(pk2 >> 20) * DD + lane * 4];
        float4 rv3 = *(const float4*)&rs[(pk3 >> 20) * DD + lane * 4];
        acc.x += dv0 * xv0.x * rv0.x + dv1 * xv1.x * rv1.x
               + dv2 * xv2.x * rv2.x + dv3 * xv3.x * rv3.x;
        acc.y += dv0 * xv0.y * rv0.y + dv1 * xv1.y * rv1.y
               + dv2 * xv2.y * rv2.y + dv3 * xv3.y * rv3.y;
        acc.z += dv0 * xv0.z * rv0.z + dv1 * xv1.z * rv1.z
               + dv2 * xv2.z * rv2.z + dv3 * xv3.z * rv3.z;
        acc.w += dv0 * xv0.w * rv0.w + dv1 * xv1.w * rv1.w
               + dv2 * xv2.w * rv2.w + dv3 * xv3.w * rv3.w;
    }
    for (; p < end; p++) {
        int pk = nbr[p];
        int m = pk & 0xFFFFF;
        float dv = dinv[m];
        float4 xv = x4[m * 32 + lane];
        float4 rv = *(const float4*)&rs[(pk >> 20) * DD + lane * 4];
        acc.x += dv * xv.x * rv.x;
        acc.y += dv * xv.y * rv.y;
        acc.z += dv * xv.z * rv.z;
        acc.w += dv * xv.w * rv.w;
    }
    float own = dinv[n];
    acc.x *= own; acc.y *= own; acc.z *= own; acc.w *= own;
    *(float4*)&agg[(size_t)n * DD + lane * 4] = acc;
}

// ---------------- fused 3-chunk GEMM + bias + BN partial stats --------------
__global__ __launch_bounds__(256)
void k_gemm(const float* __restrict__ x,
            const float* __restrict__ B0, const float* __restrict__ B1,
            const float* __restrict__ B2,
            const float* __restrict__ lr, const float* __restrict__ bias,
            int layer) {
    __shared__ float Ast[32][132];
    __shared__ float Bs [32][132];

    const int tid = threadIdx.x;
    const int tx = tid & 15;
    const int ty = tid >> 4;
    const int rowBase = blockIdx.x * 128;

    unsigned long long acc[8][4];
#pragma unroll
    for (int i = 0; i < 8; i++)
#pragma unroll
        for (int j = 0; j < 4; j++) acc[i][j] = 0ULL;

    for (int c = 0; c < 3; c++) {
        const float* A = (c == 0) ? g_agg_in : (c == 1) ? g_agg_out : x;
        const float* B = (c == 0) ? B0 : (c == 1) ? B1 : B2;
        for (int ks = 0; ks < 4; ks++) {
            __syncthreads();
            {
                int k4 = tid & 7;
                int r0 = tid >> 3;
#pragma unroll
                for (int rr = 0; rr < 4; rr++) {
                    int row = r0 + rr * 32;
                    int grow = rowBase + row;
                    float4 v = make_float4(0.f, 0.f, 0.f, 0.f);
                    if (grow < NN)
                        v = *(const float4*)&A[(size_t)grow * DD + ks * 32 + k4 * 4];
                    Ast[k4 * 4 + 0][row] = v.x;
                    Ast[k4 * 4 + 1][row] = v.y;
                    Ast[k4 * 4 + 2][row] = v.z;
                    Ast[k4 * 4 + 3][row] = v.w;
                }
            }
            {
                int c4 = tid & 31;
                int k0 = tid >> 5;
#pragma unroll
                for (int p = 0; p < 4; p++) {
                    int kk = k0 + p * 8;
                    int gk = ks * 32 + kk;
                    float4 v = *(const float4*)&B[gk * DD + c4 * 4];
                    if (c == 2) {
                        float sc = lr[gk];
                        v.x *= sc; v.y *= sc; v.z *= sc; v.w *= sc;
                    }
                    *(float4*)&Bs[kk][c4 * 4] = v;
                }
            }
            __syncthreads();
#pragma unroll 4
            for (int k = 0; k < 32; k++) {
                float4 a0 = *(const float4*)&Ast[k][ty * 8];
                float4 a1 = *(const float4*)&Ast[k][ty * 8 + 4];
                float4 b0 = *(const float4*)&Bs[k][tx * 8];
                float4 b1 = *(const float4*)&Bs[k][tx * 8 + 4];
                unsigned long long bp[4];
                bp[0] = pk2(b0.x, b0.y); bp[1] = pk2(b0.z, b0.w);
                bp[2] = pk2(b1.x, b1.y); bp[3] = pk2(b1.z, b1.w);
                float av[8] = {a0.x, a0.y, a0.z, a0.w, a1.x, a1.y, a1.z, a1.w};
#pragma unroll
                for (int i = 0; i < 8; i++) {
                    unsigned long long ap = pk2(av[i], av[i]);
#pragma unroll
                    for (int j = 0; j < 4; j++) fma2(acc[i][j], ap, bp[j]);
                }
            }
        }
    }

    const float third = 1.0f / 3.0f;
    float scol[8], qcol[8];
#pragma unroll
    for (int jj = 0; jj < 8; jj++) { scol[jj] = 0.f; qcol[jj] = 0.f; }
#pragma unroll
    for (int i = 0; i < 8; i++) {
        int grow = rowBase + ty * 8 + i;
        if (grow < NN) {
#pragma unroll
            for (int j = 0; j < 4; j++) {
                float lo, hi;
                upk2(acc[i][j], lo, hi);
                int col = tx * 8 + j * 2;
                lo = lo * third + bias[col];
                hi = hi * third + bias[col + 1];
                g_out[(size_t)grow * DD + col]     = lo;
                g_out[(size_t)grow * DD + col + 1] = hi;
                scol[j * 2]     += lo;  qcol[j * 2]     += lo * lo;
                scol[j * 2 + 1] += hi;  qcol[j * 2 + 1] += hi * hi;
            }
        }
    }

    __syncthreads();
    float* ssum = &Ast[0][0];
    float* ssq  = &Ast[0][0] + DD;
    if (tid < DD) { ssum[tid] = 0.f; ssq[tid] = 0.f; }
    __syncthreads();
#pragma unroll
    for (int jj = 0; jj < 8; jj++) {
        int col = tx * 8 + jj;
        atomicAdd(&ssum[col], scol[jj]);
        atomicAdd(&ssq[col], qcol[jj]);
    }
    __syncthreads();
    if (tid < DD) {
        atomicAdd(&g_stats[layer][tid], ssum[tid]);
        atomicAdd(&g_stats[layer][DD + tid], ssq[tid]);
    }
}

// ---------------- batchnorm normalize + fast tanh (float4) ------------------
__global__ __launch_bounds__(256)
void k_bn_tanh(float* __restrict__ xo, int layer) {
    int cg = threadIdx.x & 31;
    int rr = threadIdx.x >> 5;
    int c0 = cg * 4;
    float m0 = g_stats[layer][c0],     m1 = g_stats[layer][c0 + 1];
    float m2 = g_stats[layer][c0 + 2], m3 = g_stats[layer][c0 + 3];
    float q0 = g_stats[layer][DD + c0],     q1 = g_stats[layer][DD + c0 + 1];
    float q2 = g_stats[layer][DD + c0 + 2], q3 = g_stats[layer][DD + c0 + 3];
    const float invN = 1.0f / NN;
    m0 *= invN; m1 *= invN; m2 *= invN; m3 *= invN;
    float i0 = rsqrtf(q0 * invN - m0 * m0 + EPS);
    float i1 = rsqrtf(q1 * invN - m1 * m1 + EPS);
    float i2 = rsqrtf(q2 * invN - m2 * m2 + EPS);
    float i3 = rsqrtf(q3 * invN - m3 * m3 + EPS);
    for (int n = blockIdx.x * 8 + rr; n < NN; n += gridDim.x * 8) {
        float4 v = *(const float4*)&g_out[(size_t)n * DD + c0];
        v.x = fast_tanh((v.x - m0) * i0);
        v.y = fast_tanh((v.y - m1) * i1);
        v.z = fast_tanh((v.z - m2) * i2);
        v.w = fast_tanh((v.w - m3) * i3);
        *(float4*)&xo[(size_t)n * DD + c0] = v;
    }
}

// ---------------- relation transform r' = r @ W -----------------------------
__global__ void k_relmm(const float* __restrict__ r, const float* __restrict__ w,
                        float* __restrict__ ro) {
    int idx = blockIdx.x * blockDim.x + threadIdx.x;
    if (idx < RR * DD) {
        int i = idx / DD, j = idx % DD;
        float s = 0.f;
        for (int k = 0; k < DD; k++) s += r[i * DD + k] * w[k * DD + j];
        ro[idx] = s;
    }
}

// ---------------- launch ----------------------------------------------------
extern "C" void kernel_launch(void* const* d_in, const int* in_sizes, int n_in,
                              void* d_out, int out_size) {
    const float* x0       = (const float*)d_in[0];
    const float* r0       = (const float*)d_in[1];
    const float* w_in     = (const float*)d_in[2];
    const float* w_out    = (const float*)d_in[3];
    const float* w_loop   = (const float*)d_in[4];
    const float* w_rel    = (const float*)d_in[5];
    const float* loop_rel = (const float*)d_in[6];
    const float* bias     = (const float*)d_in[7];
    const int*   esrc     = (const int*)d_in[8];
    const int*   edst     = (const int*)d_in[9];
    const int*   etyp     = (const int*)d_in[10];

    float* out      = (float*)d_out;
    float* x_final  = out;
    float* r_final  = out + (size_t)NN * DD;

    const int GEMM_BLOCKS = (NN + 127) / 128;
    const int AGG_BLOCKS  = (2 * NN + 7) / 8;

    // idx 0..2: zero + fake CSR (probe input; all rewritten later)
    k_zero_deg<<<256, 256>>>();
    k_fake_csr<<<512, 256>>>(0);
    k_fake_csr<<<512, 256>>>(1);

    // idx 3: *** ncu PROBE *** — k_agg on fake CSR (g_agg_* rewritten below)
    k_agg<<<AGG_BLOCKS, 256>>>(x0, r0);

    // real graph precompute
    k_degree<<<(EE + 255) / 256, 256>>>(esrc, edst);
    k_dinv<<<(NN + 255) / 256, 256>>>();
    {
        dim3 g(SCAN_NB, 2);
        k_scan_part<<<g, SCAN_B>>>();
        k_scan_top<<<1, 512>>>();
        k_scan_fix<<<g, SCAN_B>>>();
    }
    k_scatter<<<(EE + 255) / 256, 256>>>(esrc, edst, etyp);

    // ---- layer 0 ----
    k_agg<<<AGG_BLOCKS, 256>>>(x0, r0);
    k_gemm<<<GEMM_BLOCKS, 256>>>(x0, w_in, w_out, w_loop, loop_rel, bias, 0);
    k_bn_tanh<<<512, 256>>>(g_x, 0);
    k_relmm<<<(RR * DD + 255) / 256, 256>>>(r0, w_rel, g_r1);

    // ---- layer 1 ----
    k_agg<<<AGG_BLOCKS, 256>>>(g_x, g_r1);
    k_gemm<<<GEMM_BLOCKS, 256>>>(g_x, w_in + DD * DD, w_out + DD * DD,
                                 w_loop + DD * DD, loop_rel + DD, bias + DD, 1);
    k_bn_tanh<<<512, 256>>>(x_final, 1);
    k_relmm<<<(RR * DD + 255) / 256, 256>>>(g_r1, w_rel + DD * DD, r_final);
}